// round 6
// baseline (speedup 1.0000x reference)
#include <cuda_runtime.h>
#include <cuda_bf16.h>

#define INPUT_DIM 4
#define H1 64
#define H2 32
#define BATCH 64
#define SEQ 4096
#define RING 8
#define NT 128

// ---- packed f32x2 helpers ----
__device__ __forceinline__ unsigned long long pk2(float a, float b) {
    unsigned long long r;
    asm("mov.b64 %0, {%1, %2};" : "=l"(r) : "f"(a), "f"(b));
    return r;
}
__device__ __forceinline__ void upk2(unsigned long long v, float& a, float& b) {
    asm("mov.b64 {%0, %1}, %2;" : "=f"(a), "=f"(b) : "l"(v));
}
__device__ __forceinline__ unsigned long long fma2(unsigned long long a,
                                                   unsigned long long b,
                                                   unsigned long long c) {
    unsigned long long d;
    asm("fma.rn.f32x2 %0, %1, %2, %3;" : "=l"(d) : "l"(a), "l"(b), "l"(c));
    return d;
}
__device__ __forceinline__ unsigned long long add2(unsigned long long a,
                                                   unsigned long long b) {
    unsigned long long d;
    asm("add.rn.f32x2 %0, %1, %2;" : "=l"(d) : "l"(a), "l"(b));
    return d;
}
__device__ __forceinline__ float tanh_approx(float x) {
    float y;
    asm("tanh.approx.f32 %0, %1;" : "=f"(y) : "f"(x));
    return y;
}

// ---- addressing / cluster helpers ----
__device__ __forceinline__ unsigned s2u(const void* p) {
    unsigned a;
    asm("{ .reg .u64 t; cvta.to.shared.u64 t, %1; cvt.u32.u64 %0, t; }"
        : "=r"(a) : "l"(p));
    return a;
}
__device__ __forceinline__ unsigned mapa32(unsigned saddr, unsigned rank) {
    unsigned r;
    asm("mapa.shared::cluster.u32 %0, %1, %2;" : "=r"(r) : "r"(saddr), "r"(rank));
    return r;
}
__device__ __forceinline__ void st_remote_f32(unsigned saddr, float v) {
    asm volatile("st.shared::cluster.f32 [%0], %1;" :: "r"(saddr), "f"(v) : "memory");
}
__device__ __forceinline__ void st_rel_remote_i32(unsigned saddr, int v) {
    asm volatile("st.release.cluster.shared::cluster.b32 [%0], %1;"
                 :: "r"(saddr), "r"(v) : "memory");
}
__device__ __forceinline__ int ld_acq_cluster(const int* p) {
    int v;
    asm volatile("ld.acquire.cluster.b32 %0, [%1];" : "=r"(v) : "l"(p) : "memory");
    return v;
}
__device__ __forceinline__ void mbar_init(unsigned saddr, unsigned cnt) {
    asm volatile("mbarrier.init.shared.b64 [%0], %1;" :: "r"(saddr), "r"(cnt) : "memory");
}
__device__ __forceinline__ void mbar_arrive_remote(unsigned saddr) {
    asm volatile("mbarrier.arrive.release.cluster.shared::cluster.b64 _, [%0];"
                 :: "r"(saddr) : "memory");
}
__device__ __forceinline__ unsigned mbar_try_wait(unsigned saddr, unsigned phase) {
    unsigned done;
    asm volatile(
        "{\n\t.reg .pred p;\n\t"
        "mbarrier.try_wait.parity.acquire.cluster.shared::cta.b64 p, [%1], %2;\n\t"
        "selp.b32 %0, 1, 0, p;\n\t}"
        : "=r"(done) : "r"(saddr), "r"(phase) : "memory");
    return done;
}
__device__ __forceinline__ void cluster_sync() {
    asm volatile("barrier.cluster.arrive.aligned;" ::: "memory");
    asm volatile("barrier.cluster.wait.aligned;" ::: "memory");
}

__global__ void __launch_bounds__(NT, 1) __cluster_dims__(2, 1, 1)
lstm2_kernel(const float* __restrict__ x,
             const float* __restrict__ W_ih1, const float* __restrict__ W_hh1,
             const float* __restrict__ b_ih1, const float* __restrict__ b_hh1,
             const float* __restrict__ W_ih2, const float* __restrict__ W_hh2,
             const float* __restrict__ b_ih2, const float* __restrict__ b_hh2,
             float* __restrict__ out)
{
    const int b    = blockIdx.x >> 1;
    const int rank = blockIdx.x & 1;   // 0 = L1 producer, 1 = L2 consumer
    const int tid  = threadIdx.x;

    __shared__ __align__(16) float h1loc[2][H1];       // rank0: local h1 double buffer
    __shared__ __align__(16) float h1ring[RING][H1];   // rank1: incoming h1 ring
    __shared__ __align__(16) float h2buf[2][H2];       // rank1
    __shared__ __align__(8)  unsigned long long mb[RING]; // rank1: full-slot mbarriers
    __shared__ int free_flag;                          // rank0: last step L2 freed

    if (tid == 0) {
        if (rank == 1) {
            #pragma unroll
            for (int s = 0; s < RING; ++s) mbar_init(s2u(&mb[s]), 64);
        } else {
            free_flag = -1;
        }
    }
    if (rank == 0 && (tid & 1)) h1loc[0][tid >> 1] = 0.0f;          // h1(-1)=0
    if (rank == 1 && ((tid & 3) == 0)) h2buf[0][tid >> 2] = 0.0f;   // h2(-1)=0
    __syncthreads();
    cluster_sync();   // mbarriers + buffers visible cluster-wide

    if (rank == 0) {
        // ================= Layer 1 (producer SM) =================
        const int u   = tid >> 1;
        const int par = tid & 1;
        const int rowA = par * H1 + u;        // par0: i, par1: f
        const int rowB = (2 + par) * H1 + u;  // par0: g, par1: o

        const float bS = par ? 0.5f : 1.0f;   // gateB act params (tanh for g, sigmoid for o)
        const float bA = par ? 0.5f : 1.0f;
        const float bB = par ? 0.5f : 0.0f;

        unsigned long long wA[32], wB[32], xA0, xA1, xB0, xB1;
        {
            const float2* whhA = reinterpret_cast<const float2*>(W_hh1 + rowA * H1);
            const float2* whhB = reinterpret_cast<const float2*>(W_hh1 + rowB * H1);
            #pragma unroll
            for (int k = 0; k < 32; ++k) {
                float2 v = whhA[k]; wA[k] = pk2(v.x, v.y);
                float2 w = whhB[k]; wB[k] = pk2(w.x, w.y);
            }
            const float2* wihA = reinterpret_cast<const float2*>(W_ih1 + rowA * INPUT_DIM);
            const float2* wihB = reinterpret_cast<const float2*>(W_ih1 + rowB * INPUT_DIM);
            float2 v;
            v = wihA[0]; xA0 = pk2(v.x, v.y);
            v = wihA[1]; xA1 = pk2(v.x, v.y);
            v = wihB[0]; xB0 = pk2(v.x, v.y);
            v = wihB[1]; xB1 = pk2(v.x, v.y);
        }
        const float biasA = b_ih1[rowA] + b_hh1[rowA];
        const float biasB = b_ih1[rowB] + b_hh1[rowB];

        const unsigned ring_remote = mapa32(s2u(h1ring), 1);
        const unsigned mb_remote   = mapa32(s2u(mb), 1);

        const float4* xb4 = reinterpret_cast<const float4*>(x + (size_t)b * SEQ * INPUT_DIM);
        float c = 0.0f;               // valid in par==1
        float4 xv = __ldg(xb4);       // x(0)

        #pragma unroll 1
        for (int t = 0; t < SEQ; ++t) {
            const int tn = (t + 1 < SEQ) ? (t + 1) : t;
            const float4 xv_next = __ldg(xb4 + tn);

            // backpressure: slot t&7 must be freed by L2 (covers h1(t-8))
            if (t >= RING) {
                while (ld_acq_cluster(&free_flag) < t - RING) {}
            }

            const ulonglong2* hv = reinterpret_cast<const ulonglong2*>(h1loc[t & 1]);
            const unsigned long long xp0 = pk2(xv.x, xv.y);
            const unsigned long long xp1 = pk2(xv.z, xv.w);

            unsigned long long a0 = pk2(biasA, 0.0f), a1 = 0ull, a2 = 0ull, a3 = 0ull;
            unsigned long long d0 = pk2(biasB, 0.0f), d1 = 0ull, d2 = 0ull, d3 = 0ull;
            #pragma unroll
            for (int kk = 0; kk < 8; ++kk) {
                const ulonglong2 hA = hv[2 * kk];
                const ulonglong2 hB = hv[2 * kk + 1];
                a0 = fma2(wA[4 * kk + 0], hA.x, a0);
                d0 = fma2(wB[4 * kk + 0], hA.x, d0);
                a1 = fma2(wA[4 * kk + 1], hA.y, a1);
                d1 = fma2(wB[4 * kk + 1], hA.y, d1);
                a2 = fma2(wA[4 * kk + 2], hB.x, a2);
                d2 = fma2(wB[4 * kk + 2], hB.x, d2);
                a3 = fma2(wA[4 * kk + 3], hB.y, a3);
                d3 = fma2(wB[4 * kk + 3], hB.y, d3);
            }
            a0 = fma2(xA0, xp0, a0); a1 = fma2(xA1, xp1, a1);
            d0 = fma2(xB0, xp0, d0); d1 = fma2(xB1, xp1, d1);
            a0 = add2(add2(a0, a1), add2(a2, a3));
            d0 = add2(add2(d0, d1), add2(d2, d3));
            float alo, ahi, dlo, dhi;
            upk2(a0, alo, ahi); upk2(d0, dlo, dhi);
            const float rawA = alo + ahi;
            const float rawB = dlo + dhi;

            const float sA = __fmaf_rn(0.5f, tanh_approx(0.5f * rawA), 0.5f); // sigmoid
            const float sB = __fmaf_rn(bA, tanh_approx(bS * rawB), bB);

            const float val = sA * sB;                         // par0: i*g
            const float ig  = __shfl_xor_sync(0xffffffffu, val, 1);
            c = __fmaf_rn(sA, c, ig);                          // par1: c = f*c + i*g
            const float h = sB * tanh_approx(c);               // par1: h = o*tanh(c)
            if (par) {
                h1loc[(t + 1) & 1][u] = h;
                st_remote_f32(ring_remote + (unsigned)((t & (RING - 1)) * H1 + u) * 4u, h);
                mbar_arrive_remote(mb_remote + (unsigned)(t & (RING - 1)) * 8u);
            }
            __syncthreads();
            xv = xv_next;
        }
    } else {
        // ================= Layer 2 (consumer SM) =================
        const int u = tid >> 2;
        const int q = tid & 3;
        const float actS = (q == 2) ? 1.0f : 0.5f;
        const float actA = (q == 2) ? 1.0f : 0.5f;
        const float actB = (q == 2) ? 0.0f : 0.5f;

        const int g = q * H2 + u;
        unsigned long long w2[48];
        {
            const float2* wih = reinterpret_cast<const float2*>(W_ih2 + g * H1);
            #pragma unroll
            for (int k = 0; k < 32; ++k) { const float2 v = wih[k]; w2[k] = pk2(v.x, v.y); }
            const float2* whh = reinterpret_cast<const float2*>(W_hh2 + g * H2);
            #pragma unroll
            for (int k = 0; k < 16; ++k) { const float2 v = whh[k]; w2[32 + k] = pk2(v.x, v.y); }
        }
        const float bias = b_ih2[g] + b_hh2[g];
        float* outb = out + (size_t)b * SEQ * H2;

        const unsigned mb_local    = s2u(mb);
        const unsigned flag_remote = mapa32(s2u(&free_flag), 0);

        float c = 0.0f;

        #pragma unroll 1
        for (int t = 0; t < SEQ; ++t) {
            // wait for h1(t) in ring slot t&7
            {
                const unsigned a  = mb_local + (unsigned)(t & (RING - 1)) * 8u;
                const unsigned ph = (unsigned)((t >> 3) & 1);
                while (!mbar_try_wait(a, ph)) {}
            }

            const ulonglong2* hv = reinterpret_cast<const ulonglong2*>(h1ring[t & (RING - 1)]);
            const ulonglong2* gv = reinterpret_cast<const ulonglong2*>(h2buf[t & 1]);

            unsigned long long a0 = pk2(bias, 0.0f);
            unsigned long long a1 = 0ull, a2 = 0ull, a3 = 0ull;
            #pragma unroll
            for (int kk = 0; kk < 8; ++kk) {
                const ulonglong2 hA = hv[2 * kk];
                const ulonglong2 hB = hv[2 * kk + 1];
                a0 = fma2(w2[4 * kk + 0], hA.x, a0);
                a1 = fma2(w2[4 * kk + 1], hA.y, a1);
                a2 = fma2(w2[4 * kk + 2], hB.x, a2);
                a3 = fma2(w2[4 * kk + 3], hB.y, a3);
            }
            #pragma unroll
            for (int kk = 0; kk < 4; ++kk) {
                const ulonglong2 hA = gv[2 * kk];
                const ulonglong2 hB = gv[2 * kk + 1];
                a0 = fma2(w2[32 + 4 * kk + 0], hA.x, a0);
                a1 = fma2(w2[32 + 4 * kk + 1], hA.y, a1);
                a2 = fma2(w2[32 + 4 * kk + 2], hB.x, a2);
                a3 = fma2(w2[32 + 4 * kk + 3], hB.y, a3);
            }
            a0 = add2(add2(a0, a1), add2(a2, a3));
            float lo, hi; upk2(a0, lo, hi);
            const float raw = lo + hi;

            const float act = __fmaf_rn(actA, tanh_approx(actS * raw), actB);
            const float v1 = __shfl_xor_sync(0xffffffffu, act, 1);
            const float v2 = __shfl_xor_sync(0xffffffffu, act, 2);
            const float v3 = __shfl_xor_sync(0xffffffffu, act, 3);
            c = __fmaf_rn(v1, c, act * v2);
            const float h = v3 * tanh_approx(c);

            if (q == 0) {
                h2buf[(t + 1) & 1][u] = h;
                outb[(size_t)t * H2 + u] = h;
            }
            __syncthreads();
            if (tid == 0) st_rel_remote_i32(flag_remote, t);  // release ring slot t
        }
    }

    cluster_sync();   // no CTA exits while peer may touch its smem
}

extern "C" void kernel_launch(void* const* d_in, const int* in_sizes, int n_in,
                              void* d_out, int out_size) {
    const float* x     = (const float*)d_in[0];
    const float* W_ih1 = (const float*)d_in[1];
    const float* W_hh1 = (const float*)d_in[2];
    const float* b_ih1 = (const float*)d_in[3];
    const float* b_hh1 = (const float*)d_in[4];
    const float* W_ih2 = (const float*)d_in[5];
    const float* W_hh2 = (const float*)d_in[6];
    const float* b_ih2 = (const float*)d_in[7];
    const float* b_hh2 = (const float*)d_in[8];
    float* out = (float*)d_out;

    lstm2_kernel<<<2 * BATCH, NT>>>(x, W_ih1, W_hh1, b_ih1, b_hh1,
                                    W_ih2, W_hh2, b_ih2, b_hh2, out);
}

// round 7
// speedup vs baseline: 1.1568x; 1.1568x over previous
#include <cuda_runtime.h>
#include <cuda_bf16.h>

#define INPUT_DIM 4
#define H1 64
#define H2 32
#define BATCH 64
#define SEQ 4096
#define RING 8
#define NELEM 2                 // batch elements per CTA
#define NT_L1 128
#define NT_L2 128
#define NTHREADS (NT_L1 + NT_L2)

// ---- packed f32x2 helpers ----
__device__ __forceinline__ unsigned long long pk2(float a, float b) {
    unsigned long long r;
    asm("mov.b64 %0, {%1, %2};" : "=l"(r) : "f"(a), "f"(b));
    return r;
}
__device__ __forceinline__ void upk2(unsigned long long v, float& a, float& b) {
    asm("mov.b64 {%0, %1}, %2;" : "=f"(a), "=f"(b) : "l"(v));
}
__device__ __forceinline__ unsigned long long fma2(unsigned long long a,
                                                   unsigned long long b,
                                                   unsigned long long c) {
    unsigned long long d;
    asm("fma.rn.f32x2 %0, %1, %2, %3;" : "=l"(d) : "l"(a), "l"(b), "l"(c));
    return d;
}
__device__ __forceinline__ unsigned long long add2(unsigned long long a,
                                                   unsigned long long b) {
    unsigned long long d;
    asm("add.rn.f32x2 %0, %1, %2;" : "=l"(d) : "l"(a), "l"(b));
    return d;
}
__device__ __forceinline__ float tanh_approx(float x) {
    float y;
    asm("tanh.approx.f32 %0, %1;" : "=f"(y) : "f"(x));
    return y;
}
__device__ __forceinline__ int ld_acq(const int* p) {
    int v;
    asm volatile("ld.acquire.cta.b32 %0, [%1];" : "=r"(v) : "l"(p) : "memory");
    return v;
}
__device__ __forceinline__ void st_rel(int* p, int v) {
    asm volatile("st.release.cta.b32 [%0], %1;" :: "l"(p), "r"(v) : "memory");
}
__device__ __forceinline__ void bar_sync(int id, int cnt) {
    asm volatile("bar.sync %0, %1;" :: "r"(id), "r"(cnt) : "memory");
}

__global__ void __launch_bounds__(NTHREADS, 1)
lstm2_kernel(const float* __restrict__ x,
             const float* __restrict__ W_ih1, const float* __restrict__ W_hh1,
             const float* __restrict__ b_ih1, const float* __restrict__ b_hh1,
             const float* __restrict__ W_ih2, const float* __restrict__ W_hh2,
             const float* __restrict__ b_ih2, const float* __restrict__ b_hh2,
             float* __restrict__ out)
{
    const int b0  = blockIdx.x * NELEM;   // first batch element of this CTA
    const int tid = threadIdx.x;

    __shared__ __align__(16) float h1ring[NELEM][RING][H1];
    __shared__ __align__(16) float h2buf[NELEM][2][H2];
    __shared__ int l1_done;
    __shared__ int l2_done;

    const bool isL1 = tid < NT_L1;

    if (tid == 0) { l1_done = -1; l2_done = -1; }
    if (isL1 && (tid & 1)) {
        #pragma unroll
        for (int e = 0; e < NELEM; ++e) h1ring[e][RING - 1][tid >> 1] = 0.0f;  // h1(-1)=0
    }
    if (!isL1 && (((tid - NT_L1) & 3) == 0)) {
        #pragma unroll
        for (int e = 0; e < NELEM; ++e) h2buf[e][0][(tid - NT_L1) >> 2] = 0.0f; // h2(-1)=0
    }
    __syncthreads();

    if (isL1) {
        // ======== Layer 1: 2 gates per thread, NELEM batch elements ========
        const int u   = tid >> 1;
        const int par = tid & 1;
        const int rowA = par * H1 + u;        // par0: i, par1: f
        const int rowB = (2 + par) * H1 + u;  // par0: g, par1: o

        const float bS = par ? 0.5f : 1.0f;   // gateB: g->tanh, o->sigmoid
        const float bA = par ? 0.5f : 1.0f;
        const float bB = par ? 0.5f : 0.0f;

        unsigned long long wA[32], wB[32], xA0, xA1, xB0, xB1;
        {
            const float2* whhA = reinterpret_cast<const float2*>(W_hh1 + rowA * H1);
            const float2* whhB = reinterpret_cast<const float2*>(W_hh1 + rowB * H1);
            #pragma unroll
            for (int k = 0; k < 32; ++k) {
                float2 v = whhA[k]; wA[k] = pk2(v.x, v.y);
                float2 w = whhB[k]; wB[k] = pk2(w.x, w.y);
            }
            const float2* wihA = reinterpret_cast<const float2*>(W_ih1 + rowA * INPUT_DIM);
            const float2* wihB = reinterpret_cast<const float2*>(W_ih1 + rowB * INPUT_DIM);
            float2 v;
            v = wihA[0]; xA0 = pk2(v.x, v.y);
            v = wihA[1]; xA1 = pk2(v.x, v.y);
            v = wihB[0]; xB0 = pk2(v.x, v.y);
            v = wihB[1]; xB1 = pk2(v.x, v.y);
        }
        const float biasA = b_ih1[rowA] + b_hh1[rowA];
        const float biasB = b_ih1[rowB] + b_hh1[rowB];

        const float4* xb4[NELEM];
        float4 xv[NELEM];
        float c[NELEM];
        #pragma unroll
        for (int e = 0; e < NELEM; ++e) {
            xb4[e] = reinterpret_cast<const float4*>(x + (size_t)(b0 + e) * SEQ * INPUT_DIM);
            xv[e]  = __ldg(xb4[e]);
            c[e]   = 0.0f;
        }
        int consumed = -1;

        #pragma unroll 1
        for (int t = 0; t < SEQ; ++t) {
            const int tn = (t + 1 < SEQ) ? (t + 1) : t;
            float4 xv_next[NELEM];
            #pragma unroll
            for (int e = 0; e < NELEM; ++e) xv_next[e] = __ldg(xb4[e] + tn);

            if (consumed < t - RING) {
                do { consumed = ld_acq(&l2_done); } while (consumed < t - RING);
            }

            // independent accumulators for both elements -> 16 parallel chains
            unsigned long long a0[NELEM], a1[NELEM], a2[NELEM], a3[NELEM];
            unsigned long long d0[NELEM], d1[NELEM], d2[NELEM], d3[NELEM];
            const ulonglong2* hv[NELEM];
            #pragma unroll
            for (int e = 0; e < NELEM; ++e) {
                hv[e] = reinterpret_cast<const ulonglong2*>(h1ring[e][(t + RING - 1) & (RING - 1)]);
                a0[e] = pk2(biasA, 0.0f); a1[e] = 0ull; a2[e] = 0ull; a3[e] = 0ull;
                d0[e] = pk2(biasB, 0.0f); d1[e] = 0ull; d2[e] = 0ull; d3[e] = 0ull;
            }
            #pragma unroll
            for (int kk = 0; kk < 8; ++kk) {
                #pragma unroll
                for (int e = 0; e < NELEM; ++e) {
                    const ulonglong2 hA = hv[e][2 * kk];
                    const ulonglong2 hB = hv[e][2 * kk + 1];
                    a0[e] = fma2(wA[4 * kk + 0], hA.x, a0[e]);
                    d0[e] = fma2(wB[4 * kk + 0], hA.x, d0[e]);
                    a1[e] = fma2(wA[4 * kk + 1], hA.y, a1[e]);
                    d1[e] = fma2(wB[4 * kk + 1], hA.y, d1[e]);
                    a2[e] = fma2(wA[4 * kk + 2], hB.x, a2[e]);
                    d2[e] = fma2(wB[4 * kk + 2], hB.x, d2[e]);
                    a3[e] = fma2(wA[4 * kk + 3], hB.y, a3[e]);
                    d3[e] = fma2(wB[4 * kk + 3], hB.y, d3[e]);
                }
            }
            #pragma unroll
            for (int e = 0; e < NELEM; ++e) {
                const unsigned long long xp0 = pk2(xv[e].x, xv[e].y);
                const unsigned long long xp1 = pk2(xv[e].z, xv[e].w);
                a0[e] = fma2(xA0, xp0, a0[e]); a1[e] = fma2(xA1, xp1, a1[e]);
                d0[e] = fma2(xB0, xp0, d0[e]); d1[e] = fma2(xB1, xp1, d1[e]);
                a0[e] = add2(add2(a0[e], a1[e]), add2(a2[e], a3[e]));
                d0[e] = add2(add2(d0[e], d1[e]), add2(d2[e], d3[e]));
                float alo, ahi, dlo, dhi;
                upk2(a0[e], alo, ahi); upk2(d0[e], dlo, dhi);
                const float rawA = alo + ahi;
                const float rawB = dlo + dhi;

                const float sA = __fmaf_rn(0.5f, tanh_approx(0.5f * rawA), 0.5f);
                const float sB = __fmaf_rn(bA, tanh_approx(bS * rawB), bB);

                const float val = sA * sB;                          // par0: i*g
                const float ig  = __shfl_xor_sync(0xffffffffu, val, 1);
                c[e] = __fmaf_rn(sA, c[e], ig);                     // par1: c=f*c+i*g
                const float h = sB * tanh_approx(c[e]);             // par1: h=o*tanh(c)
                if (par) h1ring[e][t & (RING - 1)][u] = h;
                xv[e] = xv_next[e];
            }

            bar_sync(1, NT_L1);
            if (tid == 0) st_rel(&l1_done, t);
        }
    } else {
        // ======== Layer 2: 1 gate per thread, NELEM batch elements ========
        const int p = tid - NT_L1;
        const int u = p >> 2;
        const int q = p & 3;
        const float actS = (q == 2) ? 1.0f : 0.5f;
        const float actA = (q == 2) ? 1.0f : 0.5f;
        const float actB = (q == 2) ? 0.0f : 0.5f;

        const int g = q * H2 + u;
        unsigned long long w2[48];
        {
            const float2* wih = reinterpret_cast<const float2*>(W_ih2 + g * H1);
            #pragma unroll
            for (int k = 0; k < 32; ++k) { const float2 v = wih[k]; w2[k] = pk2(v.x, v.y); }
            const float2* whh = reinterpret_cast<const float2*>(W_hh2 + g * H2);
            #pragma unroll
            for (int k = 0; k < 16; ++k) { const float2 v = whh[k]; w2[32 + k] = pk2(v.x, v.y); }
        }
        const float bias = b_ih2[g] + b_hh2[g];

        float* outb[NELEM];
        float c[NELEM];
        #pragma unroll
        for (int e = 0; e < NELEM; ++e) {
            outb[e] = out + (size_t)(b0 + e) * SEQ * H2;
            c[e] = 0.0f;
        }
        int avail = -1;

        #pragma unroll 1
        for (int t = 0; t < SEQ; ++t) {
            if (avail < t) {
                do { avail = ld_acq(&l1_done); } while (avail < t);
            }

            unsigned long long a0[NELEM], a1[NELEM], a2[NELEM], a3[NELEM];
            const ulonglong2* hv[NELEM];
            const ulonglong2* gv[NELEM];
            #pragma unroll
            for (int e = 0; e < NELEM; ++e) {
                hv[e] = reinterpret_cast<const ulonglong2*>(h1ring[e][t & (RING - 1)]);
                gv[e] = reinterpret_cast<const ulonglong2*>(h2buf[e][t & 1]);
                a0[e] = pk2(bias, 0.0f); a1[e] = 0ull; a2[e] = 0ull; a3[e] = 0ull;
            }
            #pragma unroll
            for (int kk = 0; kk < 8; ++kk) {
                #pragma unroll
                for (int e = 0; e < NELEM; ++e) {
                    const ulonglong2 hA = hv[e][2 * kk];
                    const ulonglong2 hB = hv[e][2 * kk + 1];
                    a0[e] = fma2(w2[4 * kk + 0], hA.x, a0[e]);
                    a1[e] = fma2(w2[4 * kk + 1], hA.y, a1[e]);
                    a2[e] = fma2(w2[4 * kk + 2], hB.x, a2[e]);
                    a3[e] = fma2(w2[4 * kk + 3], hB.y, a3[e]);
                }
            }
            #pragma unroll
            for (int kk = 0; kk < 4; ++kk) {
                #pragma unroll
                for (int e = 0; e < NELEM; ++e) {
                    const ulonglong2 hA = gv[e][2 * kk];
                    const ulonglong2 hB = gv[e][2 * kk + 1];
                    a0[e] = fma2(w2[32 + 4 * kk + 0], hA.x, a0[e]);
                    a1[e] = fma2(w2[32 + 4 * kk + 1], hA.y, a1[e]);
                    a2[e] = fma2(w2[32 + 4 * kk + 2], hB.x, a2[e]);
                    a3[e] = fma2(w2[32 + 4 * kk + 3], hB.y, a3[e]);
                }
            }
            #pragma unroll
            for (int e = 0; e < NELEM; ++e) {
                a0[e] = add2(add2(a0[e], a1[e]), add2(a2[e], a3[e]));
                float lo, hi; upk2(a0[e], lo, hi);
                const float raw = lo + hi;

                const float act = __fmaf_rn(actA, tanh_approx(actS * raw), actB);
                const float v1 = __shfl_xor_sync(0xffffffffu, act, 1);
                const float v2 = __shfl_xor_sync(0xffffffffu, act, 2);
                const float v3 = __shfl_xor_sync(0xffffffffu, act, 3);
                c[e] = __fmaf_rn(v1, c[e], act * v2);
                const float h = v3 * tanh_approx(c[e]);

                if (q == 0) {
                    h2buf[e][(t + 1) & 1][u] = h;
                    outb[e][(size_t)t * H2 + u] = h;
                }
            }
            bar_sync(2, NT_L2);
            if (tid == NT_L1) st_rel(&l2_done, t);
        }
    }
}

extern "C" void kernel_launch(void* const* d_in, const int* in_sizes, int n_in,
                              void* d_out, int out_size) {
    const float* x     = (const float*)d_in[0];
    const float* W_ih1 = (const float*)d_in[1];
    const float* W_hh1 = (const float*)d_in[2];
    const float* b_ih1 = (const float*)d_in[3];
    const float* b_hh1 = (const float*)d_in[4];
    const float* W_ih2 = (const float*)d_in[5];
    const float* W_hh2 = (const float*)d_in[6];
    const float* b_ih2 = (const float*)d_in[7];
    const float* b_hh2 = (const float*)d_in[8];
    float* out = (float*)d_out;

    lstm2_kernel<<<BATCH / NELEM, NTHREADS>>>(x, W_ih1, W_hh1, b_ih1, b_hh1,
                                              W_ih2, W_hh2, b_ih2, b_hh2, out);
}